// round 1
// baseline (speedup 1.0000x reference)
#include <cuda_runtime.h>
#include <math.h>

#define T_  4096
#define NF_ 256
#define DH_ 64
#define BH_ 64
// data_scale = DH^-0.25 = 64^-0.25
#define DS  0.35355339059327373f
// dn coefficient: 0.5 * DS^2 = 1/16
#define DNC 0.0625f

// Scratch (static __device__ — no allocations allowed)
__device__ float g_kp[(size_t)BH_ * T_ * NF_];   // 268 MB
__device__ float g_ctx[BH_ * NF_ * DH_];         // 4 MB
__device__ float g_ksum[BH_ * NF_];

// ---------------------------------------------------------------------------
__global__ void zero_kernel() {
  int idx = blockIdx.x * blockDim.x + threadIdx.x;
  const int n = BH_ * NF_ * DH_;
  for (int i = idx; i < n; i += gridDim.x * blockDim.x) g_ctx[i] = 0.f;
  if (idx < BH_ * NF_) g_ksum[idx] = 0.f;
}

// ---------------------------------------------------------------------------
// Kernel A: kp' = exp(ds*(k @ proj^T) - |k|^2/16 - rowmax)  -> g_kp
// grid (T/64, BH), 256 threads; block tile 64 tokens x 256 features
__global__ __launch_bounds__(256) void kernelA(const float* __restrict__ kin,
                                               const float* __restrict__ proj) {
  extern __shared__ float s[];
  float* p_s   = s;                 // [64][256]  proj transposed (d-major)
  float* k_s   = p_s + 64 * NF_;    // [64][64]   k transposed (d-major)
  float* dn_s  = k_s + 64 * 64;     // [64] sum of squares
  float* off_s = dn_s + 64;         // [64] combined offset
  float* rp_s  = off_s + 64;        // [64][33] rowmax partials

  const int tid = threadIdx.x;
  const int bh  = blockIdx.y;
  const int t0  = blockIdx.x * 64;

  if (tid < 64) dn_s[tid] = 0.f;
  __syncthreads();

  // proj [256][64] -> p_s[d][j]
  {
    const float4* pg = (const float4*)(proj + tid * DH_);
#pragma unroll
    for (int c = 0; c < 16; c++) {
      float4 vv = pg[c];
      p_s[(4*c+0)*NF_ + tid] = vv.x;
      p_s[(4*c+1)*NF_ + tid] = vv.y;
      p_s[(4*c+2)*NF_ + tid] = vv.z;
      p_s[(4*c+3)*NF_ + tid] = vv.w;
    }
  }
  // k tile -> k_s[d][r], plus sum-of-squares
  {
    const int r  = tid & 63;
    const int c0 = tid >> 6;
    const float* kg = kin + ((size_t)bh * T_ + t0 + r) * DH_;
#pragma unroll
    for (int it = 0; it < 4; it++) {
      int c = it * 4 + c0;
      float4 vv = *(const float4*)(kg + 4 * c);
      k_s[(4*c+0)*64 + r] = vv.x;
      k_s[(4*c+1)*64 + r] = vv.y;
      k_s[(4*c+2)*64 + r] = vv.z;
      k_s[(4*c+3)*64 + r] = vv.w;
      atomicAdd(&dn_s[r], vv.x*vv.x + vv.y*vv.y + vv.z*vv.z + vv.w*vv.w);
    }
  }
  __syncthreads();

  const int tc = tid & 31;   // feature group (8 cols)
  const int tr = tid >> 5;   // row group (8 rows)
  float acc[8][8];
#pragma unroll
  for (int i = 0; i < 8; i++)
#pragma unroll
    for (int j = 0; j < 8; j++) acc[i][j] = 0.f;

#pragma unroll 4
  for (int d = 0; d < 64; d++) {
    float a[8], b[8];
    *(float4*)&a[0] = *(const float4*)&k_s[d*64 + tr*8];
    *(float4*)&a[4] = *(const float4*)&k_s[d*64 + tr*8 + 4];
    *(float4*)&b[0] = *(const float4*)&p_s[d*NF_ + tc*8];
    *(float4*)&b[4] = *(const float4*)&p_s[d*NF_ + tc*8 + 4];
#pragma unroll
    for (int i = 0; i < 8; i++)
#pragma unroll
      for (int j = 0; j < 8; j++) acc[i][j] = fmaf(a[i], b[j], acc[i][j]);
  }

  // per-row local max over this thread's 8 cols
#pragma unroll
  for (int i = 0; i < 8; i++) {
    float m = acc[i][0];
#pragma unroll
    for (int j = 1; j < 8; j++) m = fmaxf(m, acc[i][j]);
    rp_s[(tr*8 + i)*33 + tc] = m;
  }
  __syncthreads();
  if (tid < 64) {
    float m = rp_s[tid*33];
#pragma unroll
    for (int c = 1; c < 32; c++) m = fmaxf(m, rp_s[tid*33 + c]);
    off_s[tid] = DS * m + DNC * dn_s[tid];
  }
  __syncthreads();

  float* outp = g_kp + ((size_t)bh * T_ + t0) * NF_;
#pragma unroll
  for (int i = 0; i < 8; i++) {
    int r = tr*8 + i;
    float off = off_s[r];
    float o[8];
#pragma unroll
    for (int j = 0; j < 8; j++) o[j] = __expf(fmaf(DS, acc[i][j], -off));
    *(float4*)&outp[(size_t)r*NF_ + tc*8]     = *(float4*)&o[0];
    *(float4*)&outp[(size_t)r*NF_ + tc*8 + 4] = *(float4*)&o[4];
  }
}

// ---------------------------------------------------------------------------
// Kernel B: context[j][e] += sum_t kp'[t][j] * v[t][e]; ksum[j] += sum_t kp'[t][j]
// grid (8 T-splits, BH), 256 threads; block computes full 256x64 over 512 tokens
__global__ __launch_bounds__(256) void kernelB(const float* __restrict__ vin) {
  extern __shared__ float s[];
  float* kp_s = s;               // [64][256]
  float* v_s  = s + 64 * NF_;    // [64][64]

  const int tid   = threadIdx.x;
  const int bh    = blockIdx.y;
  const int tbase = blockIdx.x * 512;
  const int ec = tid & 7;    // e group (8)
  const int jr = tid >> 3;   // j group (8)

  float acc[8][8];
  float ksp[8];
#pragma unroll
  for (int i = 0; i < 8; i++) {
    ksp[i] = 0.f;
#pragma unroll
    for (int j = 0; j < 8; j++) acc[i][j] = 0.f;
  }

  for (int ch = 0; ch < 8; ch++) {
    int t0 = tbase + ch * 64;
    __syncthreads();
    {
      const float4* src = (const float4*)(g_kp + ((size_t)bh * T_ + t0) * NF_);
      float4* dst = (float4*)kp_s;
#pragma unroll
      for (int i = 0; i < 16; i++) dst[tid + 256*i] = src[tid + 256*i];
      const float4* vsrc = (const float4*)(vin + ((size_t)bh * T_ + t0) * DH_);
      float4* vdst = (float4*)v_s;
#pragma unroll
      for (int i = 0; i < 4; i++) vdst[tid + 256*i] = vsrc[tid + 256*i];
    }
    __syncthreads();
#pragma unroll 2
    for (int t = 0; t < 64; t++) {
      float a[8], b[8];
      *(float4*)&a[0] = *(const float4*)&kp_s[t*NF_ + jr*8];
      *(float4*)&a[4] = *(const float4*)&kp_s[t*NF_ + jr*8 + 4];
      *(float4*)&b[0] = *(const float4*)&v_s[t*64 + ec*8];
      *(float4*)&b[4] = *(const float4*)&v_s[t*64 + ec*8 + 4];
#pragma unroll
      for (int i = 0; i < 8; i++)
#pragma unroll
        for (int j = 0; j < 8; j++) acc[i][j] = fmaf(a[i], b[j], acc[i][j]);
      if (ec == 0) {
#pragma unroll
        for (int i = 0; i < 8; i++) ksp[i] += a[i];
      }
    }
  }

  float* ctx = g_ctx + bh * NF_ * DH_;
#pragma unroll
  for (int i = 0; i < 8; i++)
#pragma unroll
    for (int j = 0; j < 8; j++)
      atomicAdd(&ctx[(jr*8 + i)*DH_ + ec*8 + j], acc[i][j]);
  if (ec == 0) {
#pragma unroll
    for (int i = 0; i < 8; i++) atomicAdd(&g_ksum[bh*NF_ + jr*8 + i], ksp[i]);
  }
}

// ---------------------------------------------------------------------------
// Kernel C: qp' = exp(ds*(q@proj^T) - |q|^2/16); denom = qp'.ksum;
//           out = (qp' @ context) / denom
// grid (T/64, BH), 256 threads
__global__ __launch_bounds__(256) void kernelC(const float* __restrict__ qin,
                                               const float* __restrict__ proj,
                                               float* __restrict__ outg) {
  extern __shared__ float s[];
  float* p_s   = s;                  // [64][256]  proj transposed
  float* ctx_s = p_s + 64 * NF_;     // [256][64]
  float* qp_s  = ctx_s + NF_ * DH_;  // [256][64]  qp transposed, XOR-swizzled
  float* q_s   = qp_s + NF_ * DH_;   // [64][64]   q transposed
  float* dn_s  = q_s + 64 * 64;      // [64]
  float* ks_s  = dn_s + 64;          // [256]
  float* den_s = ks_s + NF_;         // [64] inverse denominators
  float* dp_s  = den_s + 64;         // [64][33] denom partials

  const int tid = threadIdx.x;
  const int bh  = blockIdx.y;
  const int t0  = blockIdx.x * 64;

  if (tid < 64) dn_s[tid] = 0.f;
  ks_s[tid] = g_ksum[bh * NF_ + tid];
  __syncthreads();

  // proj -> p_s[d][j]
  {
    const float4* pg = (const float4*)(proj + tid * DH_);
#pragma unroll
    for (int c = 0; c < 16; c++) {
      float4 vv = pg[c];
      p_s[(4*c+0)*NF_ + tid] = vv.x;
      p_s[(4*c+1)*NF_ + tid] = vv.y;
      p_s[(4*c+2)*NF_ + tid] = vv.z;
      p_s[(4*c+3)*NF_ + tid] = vv.w;
    }
  }
  // context copy
  {
    const float4* csrc = (const float4*)(g_ctx + bh * NF_ * DH_);
    float4* cdst = (float4*)ctx_s;
#pragma unroll
    for (int i = 0; i < 16; i++) cdst[tid + 256*i] = csrc[tid + 256*i];
  }
  // q tile -> q_s[d][r] + sum of squares
  {
    const int r  = tid & 63;
    const int c0 = tid >> 6;
    const float* qg = qin + ((size_t)bh * T_ + t0 + r) * DH_;
#pragma unroll
    for (int it = 0; it < 4; it++) {
      int c = it * 4 + c0;
      float4 vv = *(const float4*)(qg + 4 * c);
      q_s[(4*c+0)*64 + r] = vv.x;
      q_s[(4*c+1)*64 + r] = vv.y;
      q_s[(4*c+2)*64 + r] = vv.z;
      q_s[(4*c+3)*64 + r] = vv.w;
      atomicAdd(&dn_s[r], vv.x*vv.x + vv.y*vv.y + vv.z*vv.z + vv.w*vv.w);
    }
  }
  __syncthreads();

  // Phase 2: dp GEMM 64x256, 8x8 per thread
  const int tc = tid & 31;
  const int tr = tid >> 5;
  {
    float acc[8][8];
#pragma unroll
    for (int i = 0; i < 8; i++)
#pragma unroll
      for (int j = 0; j < 8; j++) acc[i][j] = 0.f;

#pragma unroll 4
    for (int d = 0; d < 64; d++) {
      float a[8], b[8];
      *(float4*)&a[0] = *(const float4*)&q_s[d*64 + tr*8];
      *(float4*)&a[4] = *(const float4*)&q_s[d*64 + tr*8 + 4];
      *(float4*)&b[0] = *(const float4*)&p_s[d*NF_ + tc*8];
      *(float4*)&b[4] = *(const float4*)&p_s[d*NF_ + tc*8 + 4];
#pragma unroll
      for (int i = 0; i < 8; i++)
#pragma unroll
        for (int j = 0; j < 8; j++) acc[i][j] = fmaf(a[i], b[j], acc[i][j]);
    }

    // exp, denom partials, transposed swizzled store
#pragma unroll
    for (int i = 0; i < 8; i++) {
      int r = tr*8 + i;
      float dnr = DNC * dn_s[r];
      float pd = 0.f;
#pragma unroll
      for (int j = 0; j < 8; j++) {
        int jj = tc*8 + j;
        float e = __expf(fmaf(DS, acc[i][j], -dnr));
        pd = fmaf(e, ks_s[jj], pd);
        qp_s[jj*64 + (r ^ tc)] = e;  // swizzle: (jj>>3)&31 == tc -> conflict-free
      }
      dp_s[r*33 + tc] = pd;
    }
  }
  __syncthreads();
  if (tid < 64) {
    float dsum = dp_s[tid*33];
#pragma unroll
    for (int c = 1; c < 32; c++) dsum += dp_s[tid*33 + c];
    den_s[tid] = 1.f / dsum;
  }
  __syncthreads();

  // Phase 3: out = qp' @ context, 64x64, 4x4 per thread
  const int tc4 = tid & 15;
  const int tr4 = tid >> 4;
  float oacc[4][4];
#pragma unroll
  for (int i = 0; i < 4; i++)
#pragma unroll
    for (int j = 0; j < 4; j++) oacc[i][j] = 0.f;

#pragma unroll 4
  for (int j = 0; j < NF_; j++) {
    int sw = (j >> 3) & 31;
    float a[4], b[4];
#pragma unroll
    for (int ii = 0; ii < 4; ii++) a[ii] = qp_s[j*64 + ((tr4*4 + ii) ^ sw)];
    *(float4*)&b[0] = *(const float4*)&ctx_s[j*DH_ + tc4*4];
#pragma unroll
    for (int ii = 0; ii < 4; ii++)
#pragma unroll
      for (int jj = 0; jj < 4; jj++) oacc[ii][jj] = fmaf(a[ii], b[jj], oacc[ii][jj]);
  }

  float* og = outg + ((size_t)bh * T_ + t0) * DH_;
#pragma unroll
  for (int ii = 0; ii < 4; ii++) {
    int r = tr4*4 + ii;
    float inv = den_s[r];
    float o[4];
#pragma unroll
    for (int jj = 0; jj < 4; jj++) o[jj] = oacc[ii][jj] * inv;
    *(float4*)&og[(size_t)r*DH_ + tc4*4] = *(float4*)&o[0];
  }
}

// ---------------------------------------------------------------------------
extern "C" void kernel_launch(void* const* d_in, const int* in_sizes, int n_in,
                              void* d_out, int out_size) {
  const float* q    = (const float*)d_in[0];
  const float* k    = (const float*)d_in[1];
  const float* v    = (const float*)d_in[2];
  const float* proj = (const float*)d_in[3];
  float* out = (float*)d_out;

  const int smemA = (64*NF_ + 64*64 + 64 + 64 + 64*33) * 4;              // 90880
  const int smemB = (64*NF_ + 64*64) * 4;                                // 81920
  const int smemC = (64*NF_ + NF_*DH_ + NF_*DH_ + 64*64
                     + 64 + NF_ + 64 + 64*33) * 4;                       // 222976

  cudaFuncSetAttribute(kernelA, cudaFuncAttributeMaxDynamicSharedMemorySize, smemA);
  cudaFuncSetAttribute(kernelB, cudaFuncAttributeMaxDynamicSharedMemorySize, smemB);
  cudaFuncSetAttribute(kernelC, cudaFuncAttributeMaxDynamicSharedMemorySize, smemC);

  zero_kernel<<<256, 256>>>();
  kernelA<<<dim3(T_/64, BH_), 256, smemA>>>(k, proj);
  kernelB<<<dim3(8, BH_), 256, smemB>>>(v);
  kernelC<<<dim3(T_/64, BH_), 256, smemC>>>(q, proj, out);
}

// round 2
// speedup vs baseline: 1.0019x; 1.0019x over previous
#include <cuda_runtime.h>
#include <math.h>

#define T_  4096
#define NF_ 256
#define DH_ 64
#define BH_ 64
// data_scale = DH^-0.25 = 64^-0.25
#define DS  0.35355339059327373f
// dn coefficient: 0.5 * DS^2 = 1/16
#define DNC 0.0625f

// Scratch (static __device__ — no allocations allowed)
__device__ float g_kp[(size_t)BH_ * T_ * NF_];   // 268 MB
__device__ float g_ctx[BH_ * NF_ * DH_];         // 4 MB
__device__ float g_ksum[BH_ * NF_];

// ---------------------------------------------------------------------------
__global__ void zero_kernel() {
  int idx = blockIdx.x * blockDim.x + threadIdx.x;
  const int n = BH_ * NF_ * DH_;
  for (int i = idx; i < n; i += gridDim.x * blockDim.x) g_ctx[i] = 0.f;
  if (idx < BH_ * NF_) g_ksum[idx] = 0.f;
}

// ---------------------------------------------------------------------------
// Kernel A: kp' = exp(ds*(k @ proj^T) - |k|^2/16 - rowmax)  -> g_kp
// grid (T/64, BH), 256 threads; block tile 64 tokens x 256 features
__global__ __launch_bounds__(256) void kernelA(const float* __restrict__ kin,
                                               const float* __restrict__ proj) {
  extern __shared__ float s[];
  float* p_s   = s;                 // [64][256]  proj transposed (d-major)
  float* k_s   = p_s + 64 * NF_;    // [64][64]   k transposed (d-major)
  float* dn_s  = k_s + 64 * 64;     // [64] sum of squares
  float* off_s = dn_s + 64;         // [64] combined offset
  float* rp_s  = off_s + 64;        // [64][33] rowmax partials

  const int tid = threadIdx.x;
  const int bh  = blockIdx.y;
  const int t0  = blockIdx.x * 64;

  if (tid < 64) dn_s[tid] = 0.f;
  __syncthreads();

  // proj [256][64] -> p_s[d][j]
  {
    const float4* pg = (const float4*)(proj + tid * DH_);
#pragma unroll
    for (int c = 0; c < 16; c++) {
      float4 vv = pg[c];
      p_s[(4*c+0)*NF_ + tid] = vv.x;
      p_s[(4*c+1)*NF_ + tid] = vv.y;
      p_s[(4*c+2)*NF_ + tid] = vv.z;
      p_s[(4*c+3)*NF_ + tid] = vv.w;
    }
  }
  // k tile -> k_s[d][r], plus sum-of-squares
  {
    const int r  = tid & 63;
    const int c0 = tid >> 6;
    const float* kg = kin + ((size_t)bh * T_ + t0 + r) * DH_;
#pragma unroll
    for (int it = 0; it < 4; it++) {
      int c = it * 4 + c0;
      float4 vv = *(const float4*)(kg + 4 * c);
      k_s[(4*c+0)*64 + r] = vv.x;
      k_s[(4*c+1)*64 + r] = vv.y;
      k_s[(4*c+2)*64 + r] = vv.z;
      k_s[(4*c+3)*64 + r] = vv.w;
      atomicAdd(&dn_s[r], vv.x*vv.x + vv.y*vv.y + vv.z*vv.z + vv.w*vv.w);
    }
  }
  __syncthreads();

  const int tc = tid & 31;   // feature group (8 cols)
  const int tr = tid >> 5;   // row group (8 rows)
  float acc[8][8];
#pragma unroll
  for (int i = 0; i < 8; i++)
#pragma unroll
    for (int j = 0; j < 8; j++) acc[i][j] = 0.f;

#pragma unroll 4
  for (int d = 0; d < 64; d++) {
    float a[8], b[8];
    *(float4*)&a[0] = *(const float4*)&k_s[d*64 + tr*8];
    *(float4*)&a[4] = *(const float4*)&k_s[d*64 + tr*8 + 4];
    *(float4*)&b[0] = *(const float4*)&p_s[d*NF_ + tc*8];
    *(float4*)&b[4] = *(const float4*)&p_s[d*NF_ + tc*8 + 4];
#pragma unroll
    for (int i = 0; i < 8; i++)
#pragma unroll
      for (int j = 0; j < 8; j++) acc[i][j] = fmaf(a[i], b[j], acc[i][j]);
  }

  // per-row local max over this thread's 8 cols
#pragma unroll
  for (int i = 0; i < 8; i++) {
    float m = acc[i][0];
#pragma unroll
    for (int j = 1; j < 8; j++) m = fmaxf(m, acc[i][j]);
    rp_s[(tr*8 + i)*33 + tc] = m;
  }
  __syncthreads();
  if (tid < 64) {
    float m = rp_s[tid*33];
#pragma unroll
    for (int c = 1; c < 32; c++) m = fmaxf(m, rp_s[tid*33 + c]);
    off_s[tid] = DS * m + DNC * dn_s[tid];
  }
  __syncthreads();

  float* outp = g_kp + ((size_t)bh * T_ + t0) * NF_;
#pragma unroll
  for (int i = 0; i < 8; i++) {
    int r = tr*8 + i;
    float off = off_s[r];
    float o[8];
#pragma unroll
    for (int j = 0; j < 8; j++) o[j] = __expf(fmaf(DS, acc[i][j], -off));
    *(float4*)&outp[(size_t)r*NF_ + tc*8]     = *(float4*)&o[0];
    *(float4*)&outp[(size_t)r*NF_ + tc*8 + 4] = *(float4*)&o[4];
  }
}

// ---------------------------------------------------------------------------
// Kernel B: context[j][e] += sum_t kp'[t][j] * v[t][e]; ksum[j] += sum_t kp'[t][j]
// grid (8 T-splits, BH), 256 threads; block computes full 256x64 over 512 tokens
__global__ __launch_bounds__(256) void kernelB(const float* __restrict__ vin) {
  extern __shared__ float s[];
  float* kp_s = s;               // [64][256]
  float* v_s  = s + 64 * NF_;    // [64][64]

  const int tid   = threadIdx.x;
  const int bh    = blockIdx.y;
  const int tbase = blockIdx.x * 512;
  const int ec = tid & 7;    // e group (8)
  const int jr = tid >> 3;   // j group (8)

  float acc[8][8];
  float ksp[8];
#pragma unroll
  for (int i = 0; i < 8; i++) {
    ksp[i] = 0.f;
#pragma unroll
    for (int j = 0; j < 8; j++) acc[i][j] = 0.f;
  }

  for (int ch = 0; ch < 8; ch++) {
    int t0 = tbase + ch * 64;
    __syncthreads();
    {
      const float4* src = (const float4*)(g_kp + ((size_t)bh * T_ + t0) * NF_);
      float4* dst = (float4*)kp_s;
#pragma unroll
      for (int i = 0; i < 16; i++) dst[tid + 256*i] = src[tid + 256*i];
      const float4* vsrc = (const float4*)(vin + ((size_t)bh * T_ + t0) * DH_);
      float4* vdst = (float4*)v_s;
#pragma unroll
      for (int i = 0; i < 4; i++) vdst[tid + 256*i] = vsrc[tid + 256*i];
    }
    __syncthreads();
#pragma unroll 2
    for (int t = 0; t < 64; t++) {
      float a[8], b[8];
      *(float4*)&a[0] = *(const float4*)&kp_s[t*NF_ + jr*8];
      *(float4*)&a[4] = *(const float4*)&kp_s[t*NF_ + jr*8 + 4];
      *(float4*)&b[0] = *(const float4*)&v_s[t*64 + ec*8];
      *(float4*)&b[4] = *(const float4*)&v_s[t*64 + ec*8 + 4];
#pragma unroll
      for (int i = 0; i < 8; i++)
#pragma unroll
        for (int j = 0; j < 8; j++) acc[i][j] = fmaf(a[i], b[j], acc[i][j]);
      if (ec == 0) {
#pragma unroll
        for (int i = 0; i < 8; i++) ksp[i] += a[i];
      }
    }
  }

  float* ctx = g_ctx + bh * NF_ * DH_;
#pragma unroll
  for (int i = 0; i < 8; i++)
#pragma unroll
    for (int j = 0; j < 8; j++)
      atomicAdd(&ctx[(jr*8 + i)*DH_ + ec*8 + j], acc[i][j]);
  if (ec == 0) {
#pragma unroll
    for (int i = 0; i < 8; i++) atomicAdd(&g_ksum[bh*NF_ + jr*8 + i], ksp[i]);
  }
}

// ---------------------------------------------------------------------------
// Kernel C: qp' = exp(ds*(q@proj^T) - |q|^2/16); denom = qp'.ksum;
//           out = (qp' @ context) / denom
// grid (T/64, BH), 256 threads
__global__ __launch_bounds__(256) void kernelC(const float* __restrict__ qin,
                                               const float* __restrict__ proj,
                                               float* __restrict__ outg) {
  extern __shared__ float s[];
  float* p_s   = s;                  // [64][256]  proj transposed
  float* ctx_s = p_s + 64 * NF_;     // [256][64]
  float* qp_s  = ctx_s + NF_ * DH_;  // [256][64]  qp transposed, XOR-swizzled
  float* q_s   = qp_s + NF_ * DH_;   // [64][64]   q transposed
  float* dn_s  = q_s + 64 * 64;      // [64]
  float* ks_s  = dn_s + 64;          // [256]
  float* den_s = ks_s + NF_;         // [64] inverse denominators
  float* dp_s  = den_s + 64;         // [64][33] denom partials

  const int tid = threadIdx.x;
  const int bh  = blockIdx.y;
  const int t0  = blockIdx.x * 64;

  if (tid < 64) dn_s[tid] = 0.f;
  ks_s[tid] = g_ksum[bh * NF_ + tid];
  __syncthreads();

  // proj -> p_s[d][j]
  {
    const float4* pg = (const float4*)(proj + tid * DH_);
#pragma unroll
    for (int c = 0; c < 16; c++) {
      float4 vv = pg[c];
      p_s[(4*c+0)*NF_ + tid] = vv.x;
      p_s[(4*c+1)*NF_ + tid] = vv.y;
      p_s[(4*c+2)*NF_ + tid] = vv.z;
      p_s[(4*c+3)*NF_ + tid] = vv.w;
    }
  }
  // context copy
  {
    const float4* csrc = (const float4*)(g_ctx + bh * NF_ * DH_);
    float4* cdst = (float4*)ctx_s;
#pragma unroll
    for (int i = 0; i < 16; i++) cdst[tid + 256*i] = csrc[tid + 256*i];
  }
  // q tile -> q_s[d][r] + sum of squares
  {
    const int r  = tid & 63;
    const int c0 = tid >> 6;
    const float* qg = qin + ((size_t)bh * T_ + t0 + r) * DH_;
#pragma unroll
    for (int it = 0; it < 4; it++) {
      int c = it * 4 + c0;
      float4 vv = *(const float4*)(qg + 4 * c);
      q_s[(4*c+0)*64 + r] = vv.x;
      q_s[(4*c+1)*64 + r] = vv.y;
      q_s[(4*c+2)*64 + r] = vv.z;
      q_s[(4*c+3)*64 + r] = vv.w;
      atomicAdd(&dn_s[r], vv.x*vv.x + vv.y*vv.y + vv.z*vv.z + vv.w*vv.w);
    }
  }
  __syncthreads();

  // Phase 2: dp GEMM 64x256, 8x8 per thread
  const int tc = tid & 31;
  const int tr = tid >> 5;
  {
    float acc[8][8];
#pragma unroll
    for (int i = 0; i < 8; i++)
#pragma unroll
      for (int j = 0; j < 8; j++) acc[i][j] = 0.f;

#pragma unroll 4
    for (int d = 0; d < 64; d++) {
      float a[8], b[8];
      *(float4*)&a[0] = *(const float4*)&q_s[d*64 + tr*8];
      *(float4*)&a[4] = *(const float4*)&q_s[d*64 + tr*8 + 4];
      *(float4*)&b[0] = *(const float4*)&p_s[d*NF_ + tc*8];
      *(float4*)&b[4] = *(const float4*)&p_s[d*NF_ + tc*8 + 4];
#pragma unroll
      for (int i = 0; i < 8; i++)
#pragma unroll
        for (int j = 0; j < 8; j++) acc[i][j] = fmaf(a[i], b[j], acc[i][j]);
    }

    // exp, denom partials, transposed swizzled store
#pragma unroll
    for (int i = 0; i < 8; i++) {
      int r = tr*8 + i;
      float dnr = DNC * dn_s[r];
      float pd = 0.f;
#pragma unroll
      for (int j = 0; j < 8; j++) {
        int jj = tc*8 + j;
        float e = __expf(fmaf(DS, acc[i][j], -dnr));
        pd = fmaf(e, ks_s[jj], pd);
        qp_s[jj*64 + (r ^ tc)] = e;  // swizzle: (jj>>3)&31 == tc -> conflict-free
      }
      dp_s[r*33 + tc] = pd;
    }
  }
  __syncthreads();
  if (tid < 64) {
    float dsum = dp_s[tid*33];
#pragma unroll
    for (int c = 1; c < 32; c++) dsum += dp_s[tid*33 + c];
    den_s[tid] = 1.f / dsum;
  }
  __syncthreads();

  // Phase 3: out = qp' @ context, 64x64, 4x4 per thread
  const int tc4 = tid & 15;
  const int tr4 = tid >> 4;
  float oacc[4][4];
#pragma unroll
  for (int i = 0; i < 4; i++)
#pragma unroll
    for (int j = 0; j < 4; j++) oacc[i][j] = 0.f;

#pragma unroll 4
  for (int j = 0; j < NF_; j++) {
    int sw = (j >> 3) & 31;
    float a[4], b[4];
#pragma unroll
    for (int ii = 0; ii < 4; ii++) a[ii] = qp_s[j*64 + ((tr4*4 + ii) ^ sw)];
    *(float4*)&b[0] = *(const float4*)&ctx_s[j*DH_ + tc4*4];
#pragma unroll
    for (int ii = 0; ii < 4; ii++)
#pragma unroll
      for (int jj = 0; jj < 4; jj++) oacc[ii][jj] = fmaf(a[ii], b[jj], oacc[ii][jj]);
  }

  float* og = outg + ((size_t)bh * T_ + t0) * DH_;
#pragma unroll
  for (int ii = 0; ii < 4; ii++) {
    int r = tr4*4 + ii;
    float inv = den_s[r];
    float o[4];
#pragma unroll
    for (int jj = 0; jj < 4; jj++) o[jj] = oacc[ii][jj] * inv;
    *(float4*)&og[(size_t)r*DH_ + tc4*4] = *(float4*)&o[0];
  }
}

// ---------------------------------------------------------------------------
extern "C" void kernel_launch(void* const* d_in, const int* in_sizes, int n_in,
                              void* d_out, int out_size) {
  const float* q    = (const float*)d_in[0];
  const float* k    = (const float*)d_in[1];
  const float* v    = (const float*)d_in[2];
  const float* proj = (const float*)d_in[3];
  float* out = (float*)d_out;

  const int smemA = (64*NF_ + 64*64 + 64 + 64 + 64*33) * 4;              // 90880
  const int smemB = (64*NF_ + 64*64) * 4;                                // 81920
  const int smemC = (64*NF_ + NF_*DH_ + NF_*DH_ + 64*64
                     + 64 + NF_ + 64 + 64*33) * 4;                       // 222976

  cudaFuncSetAttribute(kernelA, cudaFuncAttributeMaxDynamicSharedMemorySize, smemA);
  cudaFuncSetAttribute(kernelB, cudaFuncAttributeMaxDynamicSharedMemorySize, smemB);
  cudaFuncSetAttribute(kernelC, cudaFuncAttributeMaxDynamicSharedMemorySize, smemC);

  zero_kernel<<<256, 256>>>();
  kernelA<<<dim3(T_/64, BH_), 256, smemA>>>(k, proj);
  kernelB<<<dim3(8, BH_), 256, smemB>>>(v);
  kernelC<<<dim3(T_/64, BH_), 256, smemC>>>(q, proj, out);
}